// round 11
// baseline (speedup 1.0000x reference)
#include <cuda_runtime.h>
#include <cuda_bf16.h>

#define NN 100000
#define NE 3200000
#define DF 512
#define HID 16
#define NC 7

// gemm1: 512 rows x 16 cols x 128-k-slice per 256-thread block; thread = 2 rows x 16 cols
#define GROWS 512
#define GKS   128          // k-slice per block (split-K = 4)
#define GKC   16           // k per staged chunk
#define GXST  17           // padded xs row stride (floats)

// ---------------- scratch (no allocations allowed) ----------------
__device__ float g_deg[NN];
__device__ float g_dinv[NN];
__device__ __align__(16) float g_h1[NN * HID];   // h1s = dinv * (x @ W1), red-accumulated
__device__ __align__(16) float g_m1[NN * HID];   // sum of h1s[src] over in-edges
__device__ __align__(16) float g_t2[NN * 8];     // t2s = dinv * (h2 @ W2), padded to 8
__device__ __align__(16) float g_m2[NN * 8];     // sum of t2s[src], padded

// 128-bit global float reduction (sm_90+)
__device__ __forceinline__ void red_add_v4(float* p, float4 v) {
    asm volatile(
        "{\n\t"
        ".reg .u64 pg;\n\t"
        "cvta.to.global.u64 pg, %0;\n\t"
        "red.global.add.v4.f32 [pg], {%1,%2,%3,%4};\n\t"
        "}"
        :: "l"(p), "f"(v.x), "f"(v.y), "f"(v.z), "f"(v.w)
        : "memory");
}

__device__ __forceinline__ void ffma2(unsigned long long& acc,
                                      unsigned long long a, unsigned long long b) {
    asm("fma.rn.f32x2 %0, %1, %2, %0;" : "+l"(acc) : "l"(a), "l"(b));
}

// ---------------- K0: init accumulators (float4 stores) ----------------
__global__ void k_init() {
    int i = blockIdx.x * blockDim.x + threadIdx.x;
    float4 z = make_float4(0.f, 0.f, 0.f, 0.f);
    if (i < NN) g_deg[i] = 1.0f;          // self-loop contributes 1 to degree
    if (i < NN * 4) { ((float4*)g_m1)[i] = z; ((float4*)g_h1)[i] = z; }
    if (i < NN * 2) ((float4*)g_m2)[i] = z;
}

// ---------------- K1: in-degree ----------------
__global__ void k_deg(const int* __restrict__ ei) {
    int e = blockIdx.x * blockDim.x + threadIdx.x;
    if (e < NE) atomicAdd(&g_deg[ei[NE + e]], 1.0f);
}

// ---------------- K2: dinv ----------------
__global__ void k_dinv() {
    int i = blockIdx.x * blockDim.x + threadIdx.x;
    if (i < NN) g_dinv[i] = rsqrtf(g_deg[i]);   // deg >= 1 always
}

// ---------------- K3: h1s += dinv * (x @ W1)  (R5 config + 4 blocks/SM) -----
__global__ __launch_bounds__(256, 4) void k_gemm1(const float* __restrict__ x,
                                                  const float* __restrict__ W1) {
    __shared__ float xs[GROWS * GXST];              // 34.8 KB
    __shared__ __align__(8) float2 Wp[GKS][8];      // 8 KB (col pairs)

    int t = threadIdx.x;
    int rb = blockIdx.x >> 2;
    int ks = (blockIdx.x & 3) * GKS;
    int row0 = rb * GROWS;

    // stage W slice as col-pairs (coalesced float2 loads)
    const float2* W2p = (const float2*)W1;
    #pragma unroll
    for (int i = t; i < GKS * 8; i += 256) {
        int k = i >> 3, c = i & 7;
        Wp[k][c] = W2p[(ks + k) * 8 + c];
    }

    unsigned long long acc[2][8];
    #pragma unroll
    for (int p = 0; p < 2; p++)
        #pragma unroll
        for (int c = 0; c < 8; c++) acc[p][c] = 0ull;

    for (int ch = 0; ch < GKS / GKC; ch++) {
        __syncthreads();
        // stage x chunk: 512 rows x 16 k, row-major padded
        #pragma unroll
        for (int i = 0; i < 8; i++) {
            int lin = t + 256 * i;
            int row = lin >> 2, j = lin & 3;
            int grow = row0 + row;
            float4 v = make_float4(0.f, 0.f, 0.f, 0.f);
            if (grow < NN) v = *(const float4*)&x[grow * DF + ks + ch * GKC + j * 4];
            float* p = &xs[row * GXST + j * 4];
            p[0] = v.x; p[1] = v.y; p[2] = v.z; p[3] = v.w;
        }
        __syncthreads();
        #pragma unroll
        for (int kk = 0; kk < GKC; kk++) {
            int kL = ch * GKC + kk;
            float xa = xs[t * GXST + kk];
            float xb = xs[(t + 256) * GXST + kk];
            unsigned long long xad, xbd;
            asm("mov.b64 %0, {%1,%1};" : "=l"(xad) : "f"(xa));
            asm("mov.b64 %0, {%1,%1};" : "=l"(xbd) : "f"(xb));
            #pragma unroll
            for (int c = 0; c < 8; c++) {
                unsigned long long w = *(const unsigned long long*)&Wp[kL][c];
                ffma2(acc[0][c], xad, w);
                ffma2(acc[1][c], xbd, w);
            }
        }
    }

    #pragma unroll
    for (int p = 0; p < 2; p++) {
        int rr = row0 + t + p * 256;
        if (rr < NN) {
            float dv = g_dinv[rr];
            float f[16];
            #pragma unroll
            for (int c = 0; c < 8; c++) {
                asm("mov.b64 {%0,%1}, %2;" : "=f"(f[2 * c]), "=f"(f[2 * c + 1]) : "l"(acc[p][c]));
                f[2 * c] *= dv; f[2 * c + 1] *= dv;
            }
            red_add_v4(&g_h1[rr * HID + 0],  make_float4(f[0],  f[1],  f[2],  f[3]));
            red_add_v4(&g_h1[rr * HID + 4],  make_float4(f[4],  f[5],  f[6],  f[7]));
            red_add_v4(&g_h1[rr * HID + 8],  make_float4(f[8],  f[9],  f[10], f[11]));
            red_add_v4(&g_h1[rr * HID + 12], make_float4(f[12], f[13], f[14], f[15]));
        }
    }
}

// ---------------- K4: layer-1 scatter (4 threads/edge, unweighted) ----------
__global__ void k_scat1(const int* __restrict__ ei) {
    int t = blockIdx.x * blockDim.x + threadIdx.x;
    int e = t >> 2, sub = t & 3;
    if (e >= NE) return;
    int src = ei[e];
    int dst = ei[NE + e];
    float4 h = ((const float4*)g_h1)[src * 4 + sub];
    red_add_v4(&g_m1[dst * HID + sub * 4], h);
}

// ---------------- K5: h2 = relu(dinv*(m1 + h1s) + b1); t2s = dinv*(h2 @ W2) -
__global__ void k_layer2(const float* __restrict__ b1, const float* __restrict__ W2) {
    __shared__ float W2s[HID][8];
    __shared__ float b1s[HID];
    int t = threadIdx.x;
    if (t < HID * NC) W2s[t / NC][t % NC] = W2[t];
    if (t < HID) { W2s[t][7] = 0.0f; b1s[t] = b1[t]; }
    __syncthreads();

    int n = blockIdx.x * blockDim.x + t;
    if (n >= NN) return;
    float dv = g_dinv[n];

    float h[HID];
    #pragma unroll
    for (int j = 0; j < 4; j++) {
        float4 mv = ((const float4*)g_m1)[n * 4 + j];
        float4 hv = ((const float4*)g_h1)[n * 4 + j];
        h[4 * j + 0] = fmaxf(dv * (mv.x + hv.x) + b1s[4 * j + 0], 0.f);
        h[4 * j + 1] = fmaxf(dv * (mv.y + hv.y) + b1s[4 * j + 1], 0.f);
        h[4 * j + 2] = fmaxf(dv * (mv.z + hv.z) + b1s[4 * j + 2], 0.f);
        h[4 * j + 3] = fmaxf(dv * (mv.w + hv.w) + b1s[4 * j + 3], 0.f);
    }

    float o[8];
    #pragma unroll
    for (int c = 0; c < 8; c++) o[c] = 0.f;
    #pragma unroll
    for (int k = 0; k < HID; k++) {
        #pragma unroll
        for (int c = 0; c < 8; c++)
            o[c] += h[k] * W2s[k][c];    // col 7 stays 0
    }
    #pragma unroll
    for (int c = 0; c < 8; c++) o[c] *= dv;   // pre-scale by own dinv
    ((float4*)g_t2)[n * 2 + 0] = make_float4(o[0], o[1], o[2], o[3]);
    ((float4*)g_t2)[n * 2 + 1] = make_float4(o[4], o[5], o[6], o[7]);
}

// ---------------- K6: layer-2 scatter (2 threads/edge, unweighted) ----------
__global__ void k_scat2(const int* __restrict__ ei) {
    int t = blockIdx.x * blockDim.x + threadIdx.x;
    int e = t >> 1, sub = t & 1;
    if (e >= NE) return;
    int src = ei[e];
    int dst = ei[NE + e];
    float4 v = ((const float4*)g_t2)[src * 2 + sub];
    red_add_v4(&g_m2[dst * 8 + sub * 4], v);
}

// ---------------- K7: finalize: logits = dinv*(m2 + t2s) + b2; log_softmax --
__global__ void k_final(const float* __restrict__ b2, float* __restrict__ out) {
    int n = blockIdx.x * blockDim.x + threadIdx.x;
    if (n >= NN) return;
    float dv = g_dinv[n];

    float4 m0 = ((const float4*)g_m2)[n * 2 + 0];
    float4 m1v = ((const float4*)g_m2)[n * 2 + 1];
    float4 t0 = ((const float4*)g_t2)[n * 2 + 0];
    float4 t1 = ((const float4*)g_t2)[n * 2 + 1];

    float l[NC];
    l[0] = dv * (m0.x + t0.x) + b2[0];
    l[1] = dv * (m0.y + t0.y) + b2[1];
    l[2] = dv * (m0.z + t0.z) + b2[2];
    l[3] = dv * (m0.w + t0.w) + b2[3];
    l[4] = dv * (m1v.x + t1.x) + b2[4];
    l[5] = dv * (m1v.y + t1.y) + b2[5];
    l[6] = dv * (m1v.z + t1.z) + b2[6];

    float mx = l[0];
    #pragma unroll
    for (int c = 1; c < NC; c++) mx = fmaxf(mx, l[c]);
    float s = 0.f;
    #pragma unroll
    for (int c = 0; c < NC; c++) s += expf(l[c] - mx);
    float lse = mx + logf(s);
    #pragma unroll
    for (int c = 0; c < NC; c++) out[n * NC + c] = l[c] - lse;
}

// ---------------- launch ----------------
extern "C" void kernel_launch(void* const* d_in, const int* in_sizes, int n_in,
                              void* d_out, int out_size) {
    const float* x   = (const float*)d_in[0];
    const int*   ei  = (const int*)d_in[1];
    const float* W1  = (const float*)d_in[2];
    const float* b1  = (const float*)d_in[3];
    const float* W2  = (const float*)d_in[4];
    const float* b2  = (const float*)d_in[5];
    float*       out = (float*)d_out;

    int gblocks = ((NN + GROWS - 1) / GROWS) * 4;   // 196 * 4 = 784

    k_init<<<(NN * 4 + 255) / 256, 256>>>();
    k_deg<<<(NE + 255) / 256, 256>>>(ei);
    k_dinv<<<(NN + 255) / 256, 256>>>();
    k_gemm1<<<gblocks, 256>>>(x, W1);
    k_scat1<<<(NE * 4 + 255) / 256, 256>>>(ei);
    k_layer2<<<(NN + 255) / 256, 256>>>(b1, W2);
    k_scat2<<<(NE * 2 + 255) / 256, 256>>>(ei);
    k_final<<<(NN + 255) / 256, 256>>>(b2, out);
}

// round 12
// speedup vs baseline: 1.1363x; 1.1363x over previous
#include <cuda_runtime.h>
#include <cuda_fp16.h>
#include <cuda_bf16.h>

#define NN 100000
#define NE 3200000
#define DF 512
#define HID 16
#define NC 7

// gemm1: 512 rows x 16 cols x 128-k-slice per 256-thread block; thread = 2 rows x 16 cols
#define GROWS 512
#define GKS   128          // k-slice per block (split-K = 4)
#define GKC   16           // k per staged chunk
#define GXST  17           // padded xs row stride (floats)

// ---------------- scratch (no allocations allowed) ----------------
__device__ float g_deg[NN];
__device__ float g_dinv[NN];
__device__ __align__(16) float  g_h1[NN * HID];   // h1s = dinv*(x@W1), f32 (red target)
__device__ __align__(16) __half g_h1h[NN * HID];  // fp16 copy for edge gather
__device__ __align__(16) float  g_m1[NN * HID];   // sum of h1s[src], f32
__device__ __align__(16) __half g_t2h[NN * 8];    // t2s = dinv*(h2@W2), fp16, padded to 8
__device__ __align__(16) float  g_m2[NN * 8];     // sum of t2s[src], f32, padded

// 128-bit global float reduction (sm_90+)
__device__ __forceinline__ void red_add_v4(float* p, float4 v) {
    asm volatile(
        "{\n\t"
        ".reg .u64 pg;\n\t"
        "cvta.to.global.u64 pg, %0;\n\t"
        "red.global.add.v4.f32 [pg], {%1,%2,%3,%4};\n\t"
        "}"
        :: "l"(p), "f"(v.x), "f"(v.y), "f"(v.z), "f"(v.w)
        : "memory");
}

__device__ __forceinline__ void ffma2(unsigned long long& acc,
                                      unsigned long long a, unsigned long long b) {
    asm("fma.rn.f32x2 %0, %1, %2, %0;" : "+l"(acc) : "l"(a), "l"(b));
}

// ---------------- K0: init accumulators (float4 stores) ----------------
__global__ void k_init() {
    int i = blockIdx.x * blockDim.x + threadIdx.x;
    float4 z = make_float4(0.f, 0.f, 0.f, 0.f);
    if (i < NN) g_deg[i] = 1.0f;          // self-loop contributes 1 to degree
    if (i < NN * 4) { ((float4*)g_m1)[i] = z; ((float4*)g_h1)[i] = z; }
    if (i < NN * 2) ((float4*)g_m2)[i] = z;
}

// ---------------- K1: in-degree ----------------
__global__ void k_deg(const int* __restrict__ ei) {
    int e = blockIdx.x * blockDim.x + threadIdx.x;
    if (e < NE) atomicAdd(&g_deg[ei[NE + e]], 1.0f);
}

// ---------------- K2: dinv ----------------
__global__ void k_dinv() {
    int i = blockIdx.x * blockDim.x + threadIdx.x;
    if (i < NN) g_dinv[i] = rsqrtf(g_deg[i]);   // deg >= 1 always
}

// ---------------- K3: h1s += dinv * (x @ W1)  (R10-exact, 74us proven) ------
__global__ __launch_bounds__(256) void k_gemm1(const float* __restrict__ x,
                                               const float* __restrict__ W1) {
    __shared__ float xs[GROWS * GXST];              // 34.8 KB
    __shared__ __align__(8) float2 Wp[GKS][8];      // 8 KB (col pairs)

    int t = threadIdx.x;
    int rb = blockIdx.x >> 2;
    int ks = (blockIdx.x & 3) * GKS;
    int row0 = rb * GROWS;

    const float2* W2p = (const float2*)W1;
    #pragma unroll
    for (int i = t; i < GKS * 8; i += 256) {
        int k = i >> 3, c = i & 7;
        Wp[k][c] = W2p[(ks + k) * 8 + c];
    }

    unsigned long long acc[2][8];
    #pragma unroll
    for (int p = 0; p < 2; p++)
        #pragma unroll
        for (int c = 0; c < 8; c++) acc[p][c] = 0ull;

    for (int ch = 0; ch < GKS / GKC; ch++) {
        __syncthreads();
        #pragma unroll
        for (int i = 0; i < 8; i++) {
            int lin = t + 256 * i;
            int row = lin >> 2, j = lin & 3;
            int grow = row0 + row;
            float4 v = make_float4(0.f, 0.f, 0.f, 0.f);
            if (grow < NN) v = *(const float4*)&x[grow * DF + ks + ch * GKC + j * 4];
            float* p = &xs[row * GXST + j * 4];
            p[0] = v.x; p[1] = v.y; p[2] = v.z; p[3] = v.w;
        }
        __syncthreads();
        #pragma unroll
        for (int kk = 0; kk < GKC; kk++) {
            int kL = ch * GKC + kk;
            float xa = xs[t * GXST + kk];
            float xb = xs[(t + 256) * GXST + kk];
            unsigned long long xad, xbd;
            asm("mov.b64 %0, {%1,%1};" : "=l"(xad) : "f"(xa));
            asm("mov.b64 %0, {%1,%1};" : "=l"(xbd) : "f"(xb));
            #pragma unroll
            for (int c = 0; c < 8; c++) {
                unsigned long long w = *(const unsigned long long*)&Wp[kL][c];
                ffma2(acc[0][c], xad, w);
                ffma2(acc[1][c], xbd, w);
            }
        }
    }

    #pragma unroll
    for (int p = 0; p < 2; p++) {
        int rr = row0 + t + p * 256;
        if (rr < NN) {
            float dv = g_dinv[rr];
            float f[16];
            #pragma unroll
            for (int c = 0; c < 8; c++) {
                asm("mov.b64 {%0,%1}, %2;" : "=f"(f[2 * c]), "=f"(f[2 * c + 1]) : "l"(acc[p][c]));
                f[2 * c] *= dv; f[2 * c + 1] *= dv;
            }
            red_add_v4(&g_h1[rr * HID + 0],  make_float4(f[0],  f[1],  f[2],  f[3]));
            red_add_v4(&g_h1[rr * HID + 4],  make_float4(f[4],  f[5],  f[6],  f[7]));
            red_add_v4(&g_h1[rr * HID + 8],  make_float4(f[8],  f[9],  f[10], f[11]));
            red_add_v4(&g_h1[rr * HID + 12], make_float4(f[12], f[13], f[14], f[15]));
        }
    }
}

// ---------------- K3b: convert h1 f32 -> fp16 copy (coalesced) --------------
__global__ void k_cvt() {
    int i = blockIdx.x * blockDim.x + threadIdx.x;   // one per 8 elems
    if (i >= NN * 2) return;
    float4 a = ((const float4*)g_h1)[i * 2 + 0];
    float4 b = ((const float4*)g_h1)[i * 2 + 1];
    __half2 h0 = __float22half2_rn(make_float2(a.x, a.y));
    __half2 h1 = __float22half2_rn(make_float2(a.z, a.w));
    __half2 h2 = __float22half2_rn(make_float2(b.x, b.y));
    __half2 h3 = __float22half2_rn(make_float2(b.z, b.w));
    uint4 o;
    o.x = *(unsigned*)&h0; o.y = *(unsigned*)&h1;
    o.z = *(unsigned*)&h2; o.w = *(unsigned*)&h3;
    ((uint4*)g_h1h)[i] = o;
}

// ---------------- K4: layer-1 scatter (4 threads/edge, fp16 gather) ---------
__global__ void k_scat1(const int* __restrict__ ei) {
    int t = blockIdx.x * blockDim.x + threadIdx.x;
    int e = t >> 2, sub = t & 3;
    if (e >= NE) return;
    int src = ei[e];
    int dst = ei[NE + e];
    uint2 raw = ((const uint2*)g_h1h)[src * 4 + sub];   // 4 halves = 8B
    float2 fa = __half22float2(*(__half2*)&raw.x);
    float2 fb = __half22float2(*(__half2*)&raw.y);
    red_add_v4(&g_m1[dst * HID + sub * 4], make_float4(fa.x, fa.y, fb.x, fb.y));
}

// ---------------- K5: h2 = relu(dinv*(m1 + h1s) + b1); t2h = dinv*(h2 @ W2) -
__global__ void k_layer2(const float* __restrict__ b1, const float* __restrict__ W2) {
    __shared__ float W2s[HID][8];
    __shared__ float b1s[HID];
    int t = threadIdx.x;
    if (t < HID * NC) W2s[t / NC][t % NC] = W2[t];
    if (t < HID) { W2s[t][7] = 0.0f; b1s[t] = b1[t]; }
    __syncthreads();

    int n = blockIdx.x * blockDim.x + t;
    if (n >= NN) return;
    float dv = g_dinv[n];

    float h[HID];
    #pragma unroll
    for (int j = 0; j < 4; j++) {
        float4 mv = ((const float4*)g_m1)[n * 4 + j];
        float4 hv = ((const float4*)g_h1)[n * 4 + j];
        h[4 * j + 0] = fmaxf(dv * (mv.x + hv.x) + b1s[4 * j + 0], 0.f);
        h[4 * j + 1] = fmaxf(dv * (mv.y + hv.y) + b1s[4 * j + 1], 0.f);
        h[4 * j + 2] = fmaxf(dv * (mv.z + hv.z) + b1s[4 * j + 2], 0.f);
        h[4 * j + 3] = fmaxf(dv * (mv.w + hv.w) + b1s[4 * j + 3], 0.f);
    }

    float o[8];
    #pragma unroll
    for (int c = 0; c < 8; c++) o[c] = 0.f;
    #pragma unroll
    for (int k = 0; k < HID; k++) {
        #pragma unroll
        for (int c = 0; c < 8; c++)
            o[c] += h[k] * W2s[k][c];    // col 7 stays 0
    }
    #pragma unroll
    for (int c = 0; c < 8; c++) o[c] *= dv;   // pre-scale by own dinv

    __half2 p0 = __float22half2_rn(make_float2(o[0], o[1]));
    __half2 p1 = __float22half2_rn(make_float2(o[2], o[3]));
    __half2 p2 = __float22half2_rn(make_float2(o[4], o[5]));
    __half2 p3 = __float22half2_rn(make_float2(o[6], o[7]));
    uint4 ov;
    ov.x = *(unsigned*)&p0; ov.y = *(unsigned*)&p1;
    ov.z = *(unsigned*)&p2; ov.w = *(unsigned*)&p3;
    ((uint4*)g_t2h)[n] = ov;
}

// ---------------- K6: layer-2 scatter (2 threads/edge, fp16 gather) ---------
__global__ void k_scat2(const int* __restrict__ ei) {
    int t = blockIdx.x * blockDim.x + threadIdx.x;
    int e = t >> 1, sub = t & 1;
    if (e >= NE) return;
    int src = ei[e];
    int dst = ei[NE + e];
    uint2 raw = ((const uint2*)g_t2h)[src * 2 + sub];   // 4 halves = 8B
    float2 fa = __half22float2(*(__half2*)&raw.x);
    float2 fb = __half22float2(*(__half2*)&raw.y);
    red_add_v4(&g_m2[dst * 8 + sub * 4], make_float4(fa.x, fa.y, fb.x, fb.y));
}

// ---------------- K7: finalize: logits = dinv*(m2 + t2s) + b2; log_softmax --
__global__ void k_final(const float* __restrict__ b2, float* __restrict__ out) {
    int n = blockIdx.x * blockDim.x + threadIdx.x;
    if (n >= NN) return;
    float dv = g_dinv[n];

    float4 m0 = ((const float4*)g_m2)[n * 2 + 0];
    float4 m1v = ((const float4*)g_m2)[n * 2 + 1];
    uint4 raw = ((const uint4*)g_t2h)[n];
    float2 t0 = __half22float2(*(__half2*)&raw.x);
    float2 t1 = __half22float2(*(__half2*)&raw.y);
    float2 t2 = __half22float2(*(__half2*)&raw.z);
    float2 t3 = __half22float2(*(__half2*)&raw.w);

    float l[NC];
    l[0] = dv * (m0.x + t0.x) + b2[0];
    l[1] = dv * (m0.y + t0.y) + b2[1];
    l[2] = dv * (m0.z + t1.x) + b2[2];
    l[3] = dv * (m0.w + t1.y) + b2[3];
    l[4] = dv * (m1v.x + t2.x) + b2[4];
    l[5] = dv * (m1v.y + t2.y) + b2[5];
    l[6] = dv * (m1v.z + t3.x) + b2[6];

    float mx = l[0];
    #pragma unroll
    for (int c = 1; c < NC; c++) mx = fmaxf(mx, l[c]);
    float s = 0.f;
    #pragma unroll
    for (int c = 0; c < NC; c++) s += expf(l[c] - mx);
    float lse = mx + logf(s);
    #pragma unroll
    for (int c = 0; c < NC; c++) out[n * NC + c] = l[c] - lse;
}

// ---------------- launch ----------------
extern "C" void kernel_launch(void* const* d_in, const int* in_sizes, int n_in,
                              void* d_out, int out_size) {
    const float* x   = (const float*)d_in[0];
    const int*   ei  = (const int*)d_in[1];
    const float* W1  = (const float*)d_in[2];
    const float* b1  = (const float*)d_in[3];
    const float* W2  = (const float*)d_in[4];
    const float* b2  = (const float*)d_in[5];
    float*       out = (float*)d_out;

    int gblocks = ((NN + GROWS - 1) / GROWS) * 4;   // 196 * 4 = 784

    k_init<<<(NN * 4 + 255) / 256, 256>>>();
    k_deg<<<(NE + 255) / 256, 256>>>(ei);
    k_dinv<<<(NN + 255) / 256, 256>>>();
    k_gemm1<<<gblocks, 256>>>(x, W1);
    k_cvt<<<(NN * 2 + 255) / 256, 256>>>();
    k_scat1<<<(NE * 4 + 255) / 256, 256>>>(ei);
    k_layer2<<<(NN + 255) / 256, 256>>>(b1, W2);
    k_scat2<<<(NE * 2 + 255) / 256, 256>>>(ei);
    k_final<<<(NN + 255) / 256, 256>>>(b2, out);
}

// round 13
// speedup vs baseline: 1.3406x; 1.1799x over previous
#include <cuda_runtime.h>
#include <cuda_fp16.h>
#include <cuda_bf16.h>

#define NN 100000
#define NE 3200000
#define DF 512
#define HID 16
#define NC 7

// gemm1 (tensor core): 128 rows per 256-thread block, full K per block
#define GR   128        // rows per block
#define KCH  64         // k per staged chunk
#define XSH  72         // xs stride (halves): 144B rows, ldmatrix conflict-free
#define WSH  24         // Ws stride (halves): 48B rows

// ---------------- scratch (no allocations allowed) ----------------
__device__ float g_deg[NN];
__device__ float g_dinv[NN];
__device__ __align__(16) float g_h1[NN * HID];   // h1s = dinv*(x@W1), plain-stored
__device__ __align__(16) float g_m1[NN * HID];   // sum of h1s[src] over in-edges
__device__ __align__(16) float g_t2[NN * 8];     // t2s = dinv*(h2@W2), padded to 8
__device__ __align__(16) float g_m2[NN * 8];     // sum of t2s[src], padded

// 128-bit global float reduction (sm_90+)
__device__ __forceinline__ void red_add_v4(float* p, float4 v) {
    asm volatile(
        "{\n\t"
        ".reg .u64 pg;\n\t"
        "cvta.to.global.u64 pg, %0;\n\t"
        "red.global.add.v4.f32 [pg], {%1,%2,%3,%4};\n\t"
        "}"
        :: "l"(p), "f"(v.x), "f"(v.y), "f"(v.z), "f"(v.w)
        : "memory");
}

// ---------------- K0: init accumulators ----------------
__global__ void k_init() {
    int i = blockIdx.x * blockDim.x + threadIdx.x;
    float4 z = make_float4(0.f, 0.f, 0.f, 0.f);
    if (i < NN) g_deg[i] = 1.0f;          // self-loop contributes 1 to degree
    if (i < NN * 4) ((float4*)g_m1)[i] = z;
    if (i < NN * 2) ((float4*)g_m2)[i] = z;
}

// ---------------- K1: in-degree ----------------
__global__ void k_deg(const int* __restrict__ ei) {
    int e = blockIdx.x * blockDim.x + threadIdx.x;
    if (e < NE) atomicAdd(&g_deg[ei[NE + e]], 1.0f);
}

// ---------------- K2: dinv ----------------
__global__ void k_dinv() {
    int i = blockIdx.x * blockDim.x + threadIdx.x;
    if (i < NN) g_dinv[i] = rsqrtf(g_deg[i]);   // deg >= 1 always
}

// ---------------- K3: h1s = dinv * (x @ W1) via tensor cores ----------------
__global__ __launch_bounds__(256) void k_gemm1(const float* __restrict__ x,
                                               const float* __restrict__ W1) {
    __shared__ __align__(16) __half xs[GR * XSH];    // 18.4 KB
    __shared__ __align__(16) __half Ws[DF * WSH];    // 24.6 KB

    int t = threadIdx.x;
    int w = t >> 5, lane = t & 31;
    int row0 = blockIdx.x * GR;

    // stage full W1 (512x16 f32 -> f16), coalesced; 2048 float4, 8 per thread
    #pragma unroll
    for (int i = 0; i < 8; i++) {
        int lin = t + 256 * i;
        int r = lin >> 2, c4 = lin & 3;
        float4 v = *(const float4*)&W1[r * HID + c4 * 4];
        __half2 h0 = __floats2half2_rn(v.x, v.y);
        __half2 h1 = __floats2half2_rn(v.z, v.w);
        uint2 o; o.x = *(unsigned*)&h0; o.y = *(unsigned*)&h1;
        *(uint2*)&Ws[r * WSH + c4 * 4] = o;
    }

    float c[2][4];
    #pragma unroll
    for (int nt = 0; nt < 2; nt++)
        #pragma unroll
        for (int i = 0; i < 4; i++) c[nt][i] = 0.f;

    unsigned xs_u = (unsigned)__cvta_generic_to_shared(&xs[0]);
    unsigned ws_u = (unsigned)__cvta_generic_to_shared(&Ws[0]);

    // ldmatrix A address components (constant over loop)
    int j  = lane >> 3;            // which 8x8 matrix this lane addresses
    int ri = lane & 7;
    int arow = w * 16 + ri + (j & 1) * 8;
    int acol8 = (j >> 1) * 8;      // halves

    for (int kc = 0; kc < DF; kc += KCH) {
        __syncthreads();
        // stage x chunk: 128 rows x 64 k, f32 -> f16; 2048 float4, 8 per thread
        #pragma unroll
        for (int i = 0; i < 8; i++) {
            int lin = t + 256 * i;
            int row = lin >> 4, c4 = lin & 15;
            int grow = row0 + row;
            float4 v = make_float4(0.f, 0.f, 0.f, 0.f);
            if (grow < NN) v = *(const float4*)&x[grow * DF + kc + c4 * 4];
            __half2 h0 = __floats2half2_rn(v.x, v.y);
            __half2 h1 = __floats2half2_rn(v.z, v.w);
            uint2 o; o.x = *(unsigned*)&h0; o.y = *(unsigned*)&h1;
            *(uint2*)&xs[row * XSH + c4 * 4] = o;
        }
        __syncthreads();

        #pragma unroll
        for (int kst = 0; kst < KCH / 16; kst++) {
            // A: 16 rows x 16 k via ldmatrix.x4
            unsigned a0, a1, a2, a3;
            unsigned aaddr = xs_u + (unsigned)((arow * XSH + kst * 16 + acol8) * 2);
            asm volatile("ldmatrix.sync.aligned.m8n8.x4.shared.b16 {%0,%1,%2,%3}, [%4];"
                         : "=r"(a0), "=r"(a1), "=r"(a2), "=r"(a3) : "r"(aaddr));
            int kbase = kc + kst * 16 + (lane & 15);
            #pragma unroll
            for (int nt = 0; nt < 2; nt++) {
                // B: 16 k x 8 n via ldmatrix.x2.trans (row-major [k][n] -> col frag)
                unsigned b0, b1;
                unsigned baddr = ws_u + (unsigned)((kbase * WSH + nt * 8) * 2);
                asm volatile("ldmatrix.sync.aligned.m8n8.x2.trans.shared.b16 {%0,%1}, [%2];"
                             : "=r"(b0), "=r"(b1) : "r"(baddr));
                asm volatile("mma.sync.aligned.m16n8k16.row.col.f32.f16.f16.f32 "
                             "{%0,%1,%2,%3}, {%4,%5,%6,%7}, {%8,%9}, {%0,%1,%2,%3};"
                             : "+f"(c[nt][0]), "+f"(c[nt][1]), "+f"(c[nt][2]), "+f"(c[nt][3])
                             : "r"(a0), "r"(a1), "r"(a2), "r"(a3), "r"(b0), "r"(b1));
            }
        }
    }

    // epilogue: scale by dinv, plain store (full K per block -> no red needed)
    int r0 = row0 + w * 16 + (lane >> 2);
    int r1 = r0 + 8;
    int c0 = (lane & 3) * 2;
    if (r0 < NN) {
        float dv = g_dinv[r0];
        *(float2*)&g_h1[r0 * HID + 0 + c0] = make_float2(c[0][0] * dv, c[0][1] * dv);
        *(float2*)&g_h1[r0 * HID + 8 + c0] = make_float2(c[1][0] * dv, c[1][1] * dv);
    }
    if (r1 < NN) {
        float dv = g_dinv[r1];
        *(float2*)&g_h1[r1 * HID + 0 + c0] = make_float2(c[0][2] * dv, c[0][3] * dv);
        *(float2*)&g_h1[r1 * HID + 8 + c0] = make_float2(c[1][2] * dv, c[1][3] * dv);
    }
}

// ---------------- K4: layer-1 scatter (4 threads/edge, unweighted) ----------
__global__ void k_scat1(const int* __restrict__ ei) {
    int t = blockIdx.x * blockDim.x + threadIdx.x;
    int e = t >> 2, sub = t & 3;
    if (e >= NE) return;
    int src = ei[e];
    int dst = ei[NE + e];
    float4 h = ((const float4*)g_h1)[src * 4 + sub];
    red_add_v4(&g_m1[dst * HID + sub * 4], h);
}

// ---------------- K5: h2 = relu(dinv*(m1 + h1s) + b1); t2s = dinv*(h2 @ W2) -
__global__ void k_layer2(const float* __restrict__ b1, const float* __restrict__ W2) {
    __shared__ float W2s[HID][8];
    __shared__ float b1s[HID];
    int t = threadIdx.x;
    if (t < HID * NC) W2s[t / NC][t % NC] = W2[t];
    if (t < HID) { W2s[t][7] = 0.0f; b1s[t] = b1[t]; }
    __syncthreads();

    int n = blockIdx.x * blockDim.x + t;
    if (n >= NN) return;
    float dv = g_dinv[n];

    float h[HID];
    #pragma unroll
    for (int j = 0; j < 4; j++) {
        float4 mv = ((const float4*)g_m1)[n * 4 + j];
        float4 hv = ((const float4*)g_h1)[n * 4 + j];
        h[4 * j + 0] = fmaxf(dv * (mv.x + hv.x) + b1s[4 * j + 0], 0.f);
        h[4 * j + 1] = fmaxf(dv * (mv.y + hv.y) + b1s[4 * j + 1], 0.f);
        h[4 * j + 2] = fmaxf(dv * (mv.z + hv.z) + b1s[4 * j + 2], 0.f);
        h[4 * j + 3] = fmaxf(dv * (mv.w + hv.w) + b1s[4 * j + 3], 0.f);
    }

    float o[8];
    #pragma unroll
    for (int c = 0; c < 8; c++) o[c] = 0.f;
    #pragma unroll
    for (int k = 0; k < HID; k++) {
        #pragma unroll
        for (int c = 0; c < 8; c++)
            o[c] += h[k] * W2s[k][c];    // col 7 stays 0
    }
    #pragma unroll
    for (int c = 0; c < 8; c++) o[c] *= dv;   // pre-scale by own dinv
    ((float4*)g_t2)[n * 2 + 0] = make_float4(o[0], o[1], o[2], o[3]);
    ((float4*)g_t2)[n * 2 + 1] = make_float4(o[4], o[5], o[6], o[7]);
}

// ---------------- K6: layer-2 scatter (2 threads/edge, unweighted) ----------
__global__ void k_scat2(const int* __restrict__ ei) {
    int t = blockIdx.x * blockDim.x + threadIdx.x;
    int e = t >> 1, sub = t & 1;
    if (e >= NE) return;
    int src = ei[e];
    int dst = ei[NE + e];
    float4 v = ((const float4*)g_t2)[src * 2 + sub];
    red_add_v4(&g_m2[dst * 8 + sub * 4], v);
}

// ---------------- K7: finalize: logits = dinv*(m2 + t2s) + b2; log_softmax --
__global__ void k_final(const float* __restrict__ b2, float* __restrict__ out) {
    int n = blockIdx.x * blockDim.x + threadIdx.x;
    if (n >= NN) return;
    float dv = g_dinv[n];

    float4 m0 = ((const float4*)g_m2)[n * 2 + 0];
    float4 m1v = ((const float4*)g_m2)[n * 2 + 1];
    float4 t0 = ((const float4*)g_t2)[n * 2 + 0];
    float4 t1 = ((const float4*)g_t2)[n * 2 + 1];

    float l[NC];
    l[0] = dv * (m0.x + t0.x) + b2[0];
    l[1] = dv * (m0.y + t0.y) + b2[1];
    l[2] = dv * (m0.z + t0.z) + b2[2];
    l[3] = dv * (m0.w + t0.w) + b2[3];
    l[4] = dv * (m1v.x + t1.x) + b2[4];
    l[5] = dv * (m1v.y + t1.y) + b2[5];
    l[6] = dv * (m1v.z + t1.z) + b2[6];

    float mx = l[0];
    #pragma unroll
    for (int c = 1; c < NC; c++) mx = fmaxf(mx, l[c]);
    float s = 0.f;
    #pragma unroll
    for (int c = 0; c < NC; c++) s += expf(l[c] - mx);
    float lse = mx + logf(s);
    #pragma unroll
    for (int c = 0; c < NC; c++) out[n * NC + c] = l[c] - lse;
}

// ---------------- launch ----------------
extern "C" void kernel_launch(void* const* d_in, const int* in_sizes, int n_in,
                              void* d_out, int out_size) {
    const float* x   = (const float*)d_in[0];
    const int*   ei  = (const int*)d_in[1];
    const float* W1  = (const float*)d_in[2];
    const float* b1  = (const float*)d_in[3];
    const float* W2  = (const float*)d_in[4];
    const float* b2  = (const float*)d_in[5];
    float*       out = (float*)d_out;

    int gblocks = (NN + GR - 1) / GR;   // 782

    k_init<<<(NN * 4 + 255) / 256, 256>>>();
    k_deg<<<(NE + 255) / 256, 256>>>(ei);
    k_dinv<<<(NN + 255) / 256, 256>>>();
    k_gemm1<<<gblocks, 256>>>(x, W1);
    k_scat1<<<(NE * 4 + 255) / 256, 256>>>(ei);
    k_layer2<<<(NN + 255) / 256, 256>>>(b1, W2);
    k_scat2<<<(NE * 2 + 255) / 256, 256>>>(ei);
    k_final<<<(NN + 255) / 256, 256>>>(b2, out);
}